// round 7
// baseline (speedup 1.0000x reference)
#include <cuda_runtime.h>
#include <math.h>
#include <stdint.h>

#define B_    32
#define C_    384
#define Hh    32
#define Ww    32
#define N_    1024
#define S_    4
#define NE    256
#define NHEAD 6
#define HD    64
#define EPS_  1e-5f

// ---------------- scratch (device globals; no allocation) ----------------
__device__ float g_Q [B_*C_*N_];   // [b][c][n]
__device__ float g_K [B_*C_*N_];
__device__ float g_V [B_*C_*N_];   // raw v (pe fused into attention)
__device__ float g_AO[B_*N_*C_];   // attention output [b][nf][cz]
__device__ float g_P [B_*C_*N_];   // proj output [b][c][n]
__device__ float g_mean[C_];
__device__ float g_rstd[C_];

// ---------------- generic-PTX helpers ----------------
__device__ __forceinline__ uint32_t smem_u32(const void* p) {
    uint32_t a;
    asm("{ .reg .u64 t; cvta.to.shared.u64 t, %1; cvt.u32.u64 %0, t; }" : "=r"(a) : "l"(p));
    return a;
}
__device__ __forceinline__ void cp16(uint32_t dst, const void* src) {
    asm volatile("cp.async.cg.shared.global [%0], [%1], 16;" :: "r"(dst), "l"(src) : "memory");
}
#define CP_COMMIT() asm volatile("cp.async.commit_group;" ::: "memory")
#define CP_WAIT(n)  asm volatile("cp.async.wait_group %0;" :: "n"(n) : "memory")

__device__ __forceinline__ uint32_t f2tf32(float f) {
    uint32_t u;
    asm("cvt.rna.tf32.f32 %0, %1;" : "=r"(u) : "f"(f));
    return u;
}
__device__ __forceinline__ float tf32f(float f) { return __uint_as_float(f2tf32(f)); }

__device__ __forceinline__ void mma_tf32(float c[4],
    uint32_t a0, uint32_t a1, uint32_t a2, uint32_t a3, uint32_t b0, uint32_t b1)
{
    asm volatile("mma.sync.aligned.m16n8k8.row.col.f32.tf32.tf32.f32 "
        "{%0,%1,%2,%3}, {%4,%5,%6,%7}, {%8,%9}, {%0,%1,%2,%3};"
        : "+f"(c[0]), "+f"(c[1]), "+f"(c[2]), "+f"(c[3])
        : "r"(a0), "r"(a1), "r"(a2), "r"(a3), "r"(b0), "r"(b1));
}

// ---------------- K1: QKV tf32 GEMM (NN) — unchanged ----------------
#define A_STR 36
#define B_STR 136
#define A_CH  (128 * A_STR)
#define B_CH  (32 * B_STR)
#define A_TOT (2 * A_CH)
#define GS_FLOATS (A_TOT + 2 * B_CH)

__global__ __launch_bounds__(256) void qkv_mma(
    const float* __restrict__ Wq,
    const float* __restrict__ Wk,
    const float* __restrict__ Wv,
    const float* __restrict__ x)
{
    extern __shared__ float sm[];
    float* As = sm;
    float* Bs = sm + A_TOT;
    const uint32_t sb = smem_u32(sm);

    const int t   = threadIdx.x;
    const int wid = t >> 5;
    const int lane = t & 31;
    const int g  = lane >> 2;
    const int tg = lane & 3;
    const int wm = wid & 1;
    const int wn = wid >> 1;

    const int n0 = blockIdx.x * 128;
    const int y  = blockIdx.y;
    const int b  = blockIdx.z;

    const int fam = y / 3;
    const int o0 = (y % 3) * 128;
    const float* W = (fam == 0) ? Wq : (fam == 1) ? Wk : Wv;
    float* outbuf = (fam == 0) ? g_Q : (fam == 1) ? g_K : g_V;
    const float* Bp = x + (size_t)b * C_ * N_;

    float acc[4][4][4];
#pragma unroll
    for (int i = 0; i < 4; i++)
#pragma unroll
        for (int j = 0; j < 4; j++) {
            acc[i][j][0] = 0.f; acc[i][j][1] = 0.f;
            acc[i][j][2] = 0.f; acc[i][j][3] = 0.f;
        }

    auto issue = [&](int kc, int buf) {
        const int k0 = kc * 32;
        uint32_t adst = sb + (uint32_t)(buf * A_CH) * 4u;
        uint32_t bdst = sb + (uint32_t)(A_TOT + buf * B_CH) * 4u;
#pragma unroll
        for (int r = 0; r < 4; r++) {
            int i = t + r * 256;
            int row = i >> 3, c4 = (i & 7) * 4;
            cp16(adst + (uint32_t)(row * A_STR + c4) * 4u,
                 W + (size_t)(o0 + row) * C_ + k0 + c4);
        }
#pragma unroll
        for (int r = 0; r < 4; r++) {
            int i = t + r * 256;
            int row = i >> 5, c4 = (i & 31) * 4;
            cp16(bdst + (uint32_t)(row * B_STR + c4) * 4u,
                 Bp + (size_t)(k0 + row) * N_ + n0 + c4);
        }
    };

    issue(0, 0);
    CP_COMMIT();

    for (int kc = 0; kc < 12; kc++) {
        const int buf = kc & 1;
        if (kc + 1 < 12) {
            issue(kc + 1, buf ^ 1);
            CP_COMMIT();
            CP_WAIT(1);
        } else {
            CP_WAIT(0);
        }
        __syncthreads();

        const float* As_ = As + buf * A_CH;
        const float* Bs_ = Bs + buf * B_CH;

#pragma unroll
        for (int ks = 0; ks < 4; ks++) {
            const int k0 = ks * 8;
            uint32_t af[4][4], bf[4][2];
#pragma unroll
            for (int mt = 0; mt < 4; mt++) {
                const float* ap = As_ + (wm * 64 + mt * 16 + g) * A_STR + k0 + tg;
                af[mt][0] = f2tf32(ap[0]);
                af[mt][1] = f2tf32(ap[8 * A_STR]);
                af[mt][2] = f2tf32(ap[4]);
                af[mt][3] = f2tf32(ap[8 * A_STR + 4]);
            }
#pragma unroll
            for (int nt = 0; nt < 4; nt++) {
                const float* bp = Bs_ + (k0 + tg) * B_STR + wn * 32 + nt * 8 + g;
                bf[nt][0] = f2tf32(bp[0]);
                bf[nt][1] = f2tf32(bp[4 * B_STR]);
            }
#pragma unroll
            for (int mt = 0; mt < 4; mt++)
#pragma unroll
                for (int nt = 0; nt < 4; nt++)
                    mma_tf32(acc[mt][nt], af[mt][0], af[mt][1], af[mt][2], af[mt][3],
                             bf[nt][0], bf[nt][1]);
        }
        __syncthreads();
    }

    float* D = outbuf + (size_t)b * C_ * N_;
#pragma unroll
    for (int mt = 0; mt < 4; mt++) {
        const int o = o0 + wm * 64 + mt * 16 + g;
#pragma unroll
        for (int nt = 0; nt < 4; nt++) {
            const int n = n0 + wn * 32 + nt * 8 + tg * 2;
            *(float2*)(D + (size_t)o * N_ + n)       = make_float2(acc[mt][nt][0], acc[mt][nt][1]);
            *(float2*)(D + (size_t)(o + 8) * N_ + n) = make_float2(acc[mt][nt][2], acc[mt][nt][3]);
        }
    }
}

// ---------------- K4: proj tf32 GEMM (NT) — unchanged ----------------
#define P_CH (128 * A_STR)
#define PS_FLOATS (4 * P_CH)

__global__ __launch_bounds__(256) void proj_mma(const float* __restrict__ Wp)
{
    extern __shared__ float sm[];
    float* As = sm;
    float* Bs = sm + 2 * P_CH;
    const uint32_t sb = smem_u32(sm);

    const int t   = threadIdx.x;
    const int wid = t >> 5;
    const int lane = t & 31;
    const int g  = lane >> 2;
    const int tg = lane & 3;
    const int wm = wid & 1;
    const int wn = wid >> 1;

    const int n0 = blockIdx.x * 128;
    const int o0 = blockIdx.y * 128;
    const int b  = blockIdx.z;

    const float* Bp = g_AO + (size_t)b * N_ * C_;

    float acc[4][4][4];
#pragma unroll
    for (int i = 0; i < 4; i++)
#pragma unroll
        for (int j = 0; j < 4; j++) {
            acc[i][j][0] = 0.f; acc[i][j][1] = 0.f;
            acc[i][j][2] = 0.f; acc[i][j][3] = 0.f;
        }

    auto issue = [&](int kc, int buf) {
        const int k0 = kc * 32;
        uint32_t adst = sb + (uint32_t)(buf * P_CH) * 4u;
        uint32_t bdst = sb + (uint32_t)((2 + buf) * P_CH) * 4u;
#pragma unroll
        for (int r = 0; r < 4; r++) {
            int i = t + r * 256;
            int row = i >> 3, c4 = (i & 7) * 4;
            cp16(adst + (uint32_t)(row * A_STR + c4) * 4u,
                 Wp + (size_t)(o0 + row) * C_ + k0 + c4);
            cp16(bdst + (uint32_t)(row * A_STR + c4) * 4u,
                 Bp + (size_t)(n0 + row) * C_ + k0 + c4);
        }
    };

    issue(0, 0);
    CP_COMMIT();

    for (int kc = 0; kc < 12; kc++) {
        const int buf = kc & 1;
        if (kc + 1 < 12) {
            issue(kc + 1, buf ^ 1);
            CP_COMMIT();
            CP_WAIT(1);
        } else {
            CP_WAIT(0);
        }
        __syncthreads();

        const float* As_ = As + buf * P_CH;
        const float* Bs_ = Bs + buf * P_CH;

#pragma unroll
        for (int ks = 0; ks < 4; ks++) {
            const int k0 = ks * 8;
            uint32_t af[4][4], bf[4][2];
#pragma unroll
            for (int mt = 0; mt < 4; mt++) {
                const float* ap = As_ + (wm * 64 + mt * 16 + g) * A_STR + k0 + tg;
                af[mt][0] = f2tf32(ap[0]);
                af[mt][1] = f2tf32(ap[8 * A_STR]);
                af[mt][2] = f2tf32(ap[4]);
                af[mt][3] = f2tf32(ap[8 * A_STR + 4]);
            }
#pragma unroll
            for (int nt = 0; nt < 4; nt++) {
                const float* bp = Bs_ + (wn * 32 + nt * 8 + g) * A_STR + k0 + tg;
                bf[nt][0] = f2tf32(bp[0]);
                bf[nt][1] = f2tf32(bp[4]);
            }
#pragma unroll
            for (int mt = 0; mt < 4; mt++)
#pragma unroll
                for (int nt = 0; nt < 4; nt++)
                    mma_tf32(acc[mt][nt], af[mt][0], af[mt][1], af[mt][2], af[mt][3],
                             bf[nt][0], bf[nt][1]);
        }
        __syncthreads();
    }

    float* D = g_P + (size_t)b * C_ * N_;
#pragma unroll
    for (int mt = 0; mt < 4; mt++) {
        const int o = o0 + wm * 64 + mt * 16 + g;
#pragma unroll
        for (int nt = 0; nt < 4; nt++) {
            const int n = n0 + wn * 32 + nt * 8 + tg * 2;
            *(float2*)(D + (size_t)o * N_ + n)       = make_float2(acc[mt][nt][0], acc[mt][nt][1]);
            *(float2*)(D + (size_t)(o + 8) * N_ + n) = make_float2(acc[mt][nt][2], acc[mt][nt][3]);
        }
    }
}

// ---------------- K3: attention — FA2-style, register P, online softmax ----------------
// Grid (4 nt, 6 h, 128 be). 256 threads (8 warps: wm=wid&3 rows, wh=wid>>2 m-half).
// 2 m-chunks of 128; K/V streamed per chunk; Q + P + AV acc in registers.
// smem (floats): Ks[64][136]=8704, Vs[64][136]=8704 (tf32, v+pe), wsh[576],
//                rm[64], rs[64], redmax[64][2], redsum[64][2]   -> 18368 = 73472 B
#define KS2 136
#define VS2 136
#define AOFF_KS 0
#define AOFF_VS 8704
#define AOFF_WS 17408
#define AOFF_RM 17984
#define AOFF_RS 18048
#define AOFF_MX 18112
#define AOFF_SM 18240
#define ATT_FLOATS 18368

__global__ __launch_bounds__(256, 2) void attn_flash(const float* __restrict__ Wpe)
{
    extern __shared__ float sm[];
    float* Ks     = sm + AOFF_KS;
    float* Vs     = sm + AOFF_VS;
    float* wsh    = sm + AOFF_WS;
    float* rm     = sm + AOFF_RM;
    float* rs     = sm + AOFF_RS;
    float* redmax = sm + AOFF_MX;
    float* redsum = sm + AOFF_SM;
    float* exch   = Ks;               // overlay: Ks dead after last QK
    const uint32_t ks_b = smem_u32(Ks);

    const int nt = blockIdx.x;        // 0..3 : 64-row Q block
    const int h  = blockIdx.y;        // 0..5
    const int be = blockIdx.z;        // 0..127
    const int b  = be >> 2;
    const int sP = be & 3;
    const int n0 = nt * 64;

    const int t = threadIdx.x;
    const int wid = t >> 5, lane = t & 31;
    const int g = lane >> 2, tg = lane & 3;
    const int wm = wid & 3;           // row tile (16 rows)
    const int wh = wid >> 2;          // m-half of chunk (64 cols)

    const float* Qg   = g_Q + ((size_t)b * C_ + h * HD) * N_ + sP * NE;
    const float* Kg   = g_K + ((size_t)b * C_ + h * HD) * N_ + sP * NE;
    const float* Vraw = g_V + ((size_t)b * C_ + h * HD) * N_;   // global n

    // ---- Q -> registers (scaled by 1/8, tf32) ----
    uint32_t qa[8][4];
#pragma unroll
    for (int ks = 0; ks < 8; ks++) {
        int d0 = ks * 8 + tg, d1 = d0 + 4;
        int c0 = n0 + wm * 16 + g;
        qa[ks][0] = f2tf32(0.125f * Qg[(size_t)d0 * N_ + c0]);
        qa[ks][1] = f2tf32(0.125f * Qg[(size_t)d0 * N_ + c0 + 8]);
        qa[ks][2] = f2tf32(0.125f * Qg[(size_t)d1 * N_ + c0]);
        qa[ks][3] = f2tf32(0.125f * Qg[(size_t)d1 * N_ + c0 + 8]);
    }

    // ---- depthwise weights + stats init ----
    for (int i = t; i < HD * 9; i += 256)
        wsh[i] = Wpe[(h * HD) * 9 + i];
    if (t < 64) { rm[t] = -1e30f; rs[t] = 0.f; }

    const int r1 = wm * 16 + g;
    const int r2 = r1 + 8;

    float av[8][4];
#pragma unroll
    for (int i = 0; i < 8; i++) {
        av[i][0] = 0.f; av[i][1] = 0.f; av[i][2] = 0.f; av[i][3] = 0.f;
    }

    for (int ck = 0; ck < 2; ck++) {
        __syncthreads();   // smem buffers free + (first iter) wsh/rm ready

        // ---- K chunk via cp.async (coalesced) ----
#pragma unroll
        for (int j = 0; j < 8; j++) {
            int u = t + j * 256;            // 2048 float4 units: 64 d x 32 m4
            int d = u >> 5, m4 = (u & 31) * 4;
            cp16(ks_b + (uint32_t)(d * KS2 + m4) * 4u,
                 Kg + (size_t)d * N_ + ck * 128 + m4);
        }
        CP_COMMIT();

        // ---- V chunk: fused depthwise 3x3 + add, tf32-stored ----
#pragma unroll
        for (int j = 0; j < 8; j++) {
            int u = t + j * 256;
            int d = u >> 5, m4 = (u & 31) * 4;
            int ng = sP * NE + ck * 128 + m4;
            int r = ng >> 5, w0 = ng & 31;
            const float* Vrow = Vraw + (size_t)d * N_;
            const float* wp = &wsh[d * 9];
            float tap[3][6];
#pragma unroll
            for (int dr = 0; dr < 3; dr++) {
                int rr = r + dr - 1;
                bool rok = (rr >= 0 && rr < Hh);
#pragma unroll
                for (int dc = 0; dc < 6; dc++) {
                    int cc = w0 + dc - 1;
                    tap[dr][dc] = (rok && cc >= 0 && cc < Ww) ? Vrow[rr * Ww + cc] : 0.f;
                }
            }
#pragma unroll
            for (int e = 0; e < 4; e++) {
                float s = wp[0] * tap[0][e] + wp[1] * tap[0][e + 1] + wp[2] * tap[0][e + 2]
                        + wp[3] * tap[1][e] + wp[4] * tap[1][e + 1] + wp[5] * tap[1][e + 2]
                        + wp[6] * tap[2][e] + wp[7] * tap[2][e + 1] + wp[8] * tap[2][e + 2];
                Vs[d * VS2 + m4 + e] = tf32f(tap[1][e + 1] + s);
            }
        }
        CP_WAIT(0);
        __syncthreads();

        // ---- QK^T: acc[8 nf][4] over warp's 64 m-cols ----
        float acc[8][4];
#pragma unroll
        for (int i = 0; i < 8; i++) {
            acc[i][0] = 0.f; acc[i][1] = 0.f; acc[i][2] = 0.f; acc[i][3] = 0.f;
        }
#pragma unroll
        for (int ks = 0; ks < 8; ks++) {
#pragma unroll
            for (int nf = 0; nf < 8; nf++) {
                const float* bp = Ks + (ks * 8 + tg) * KS2 + wh * 64 + nf * 8 + g;
                uint32_t b0 = f2tf32(bp[0]);
                uint32_t b1 = f2tf32(bp[4 * KS2]);
                mma_tf32(acc[nf], qa[ks][0], qa[ks][1], qa[ks][2], qa[ks][3], b0, b1);
            }
        }

        // ---- online softmax (rows r1, r2) ----
        float m1 = -1e30f, m2 = -1e30f;
#pragma unroll
        for (int nf = 0; nf < 8; nf++) {
            m1 = fmaxf(m1, fmaxf(acc[nf][0], acc[nf][1]));
            m2 = fmaxf(m2, fmaxf(acc[nf][2], acc[nf][3]));
        }
        m1 = fmaxf(m1, __shfl_xor_sync(0xffffffffu, m1, 1));
        m1 = fmaxf(m1, __shfl_xor_sync(0xffffffffu, m1, 2));
        m2 = fmaxf(m2, __shfl_xor_sync(0xffffffffu, m2, 1));
        m2 = fmaxf(m2, __shfl_xor_sync(0xffffffffu, m2, 2));
        if (tg == 0) { redmax[r1 * 2 + wh] = m1; redmax[r2 * 2 + wh] = m2; }
        __syncthreads();

        float nm1 = fmaxf(rm[r1], fmaxf(redmax[r1 * 2], redmax[r1 * 2 + 1]));
        float nm2 = fmaxf(rm[r2], fmaxf(redmax[r2 * 2], redmax[r2 * 2 + 1]));
        float corr1 = __expf(rm[r1] - nm1);
        float corr2 = __expf(rm[r2] - nm2);

        float s1 = 0.f, s2 = 0.f;
#pragma unroll
        for (int nf = 0; nf < 8; nf++) {
            acc[nf][0] = __expf(acc[nf][0] - nm1);
            acc[nf][1] = __expf(acc[nf][1] - nm1);
            acc[nf][2] = __expf(acc[nf][2] - nm2);
            acc[nf][3] = __expf(acc[nf][3] - nm2);
            s1 += acc[nf][0] + acc[nf][1];
            s2 += acc[nf][2] + acc[nf][3];
        }
        s1 += __shfl_xor_sync(0xffffffffu, s1, 1);
        s1 += __shfl_xor_sync(0xffffffffu, s1, 2);
        s2 += __shfl_xor_sync(0xffffffffu, s2, 1);
        s2 += __shfl_xor_sync(0xffffffffu, s2, 2);
        if (tg == 0) { redsum[r1 * 2 + wh] = s1; redsum[r2 * 2 + wh] = s2; }

        // rescale output accumulators
#pragma unroll
        for (int nf = 0; nf < 8; nf++) {
            av[nf][0] *= corr1; av[nf][1] *= corr1;
            av[nf][2] *= corr2; av[nf][3] *= corr2;
        }
        __syncthreads();

        if (wh == 0 && tg == 0) {
            rs[r1] = rs[r1] * corr1 + redsum[r1 * 2] + redsum[r1 * 2 + 1];
            rs[r2] = rs[r2] * corr2 + redsum[r2 * 2] + redsum[r2 * 2 + 1];
            rm[r1] = nm1;
            rm[r2] = nm2;
        }

        // ---- AV: av += P (regs) x V (smem) over warp's m-half ----
#pragma unroll
        for (int ks2 = 0; ks2 < 8; ks2++) {
            uint32_t a0 = f2tf32(acc[ks2][0]);
            uint32_t a1 = f2tf32(acc[ks2][2]);
            uint32_t a2 = f2tf32(acc[ks2][1]);
            uint32_t a3 = f2tf32(acc[ks2][3]);
#pragma unroll
            for (int nf2 = 0; nf2 < 8; nf2++) {
                const float2 bv = *(const float2*)(Vs + (nf2 * 8 + g) * VS2
                                                   + wh * 64 + ks2 * 8 + 2 * tg);
                mma_tf32(av[nf2], a0, a1, a2, a3,
                         __float_as_uint(bv.x), __float_as_uint(bv.y));
            }
        }
    }

    // ---- cross-half reduction + normalize + store ----
    __syncthreads();    // Ks (exch overlay) fully dead; rs final visible
    if (wh == 1) {
#pragma unroll
        for (int nf2 = 0; nf2 < 8; nf2++) {
            exch[r1 * 72 + nf2 * 8 + 2 * tg]     = av[nf2][0];
            exch[r1 * 72 + nf2 * 8 + 2 * tg + 1] = av[nf2][1];
            exch[r2 * 72 + nf2 * 8 + 2 * tg]     = av[nf2][2];
            exch[r2 * 72 + nf2 * 8 + 2 * tg + 1] = av[nf2][3];
        }
    }
    __syncthreads();
    if (wh == 0) {
        float inv1 = 1.f / rs[r1];
        float inv2 = 1.f / rs[r2];
        float* AOb = g_AO + (size_t)b * N_ * C_;
#pragma unroll
        for (int nf2 = 0; nf2 < 8; nf2++) {
#pragma unroll
            for (int e = 0; e < 4; e++) {
                int d = nf2 * 8 + 2 * tg + (e & 1);
                int rr = (e >> 1) ? r2 : r1;
                float v = (av[nf2][e] + exch[rr * 72 + d]) * ((e >> 1) ? inv2 : inv1);
                int n = n0 + rr;
                unsigned lin = (unsigned)(h * HD + d) * NE + (unsigned)n;
                unsigned ne2 = lin / C_;
                unsigned cz  = lin - ne2 * C_;
                unsigned nf3 = ne2 * S_ + (unsigned)sP;
                AOb[(size_t)nf3 * C_ + cz] = v;
            }
        }
    }
}

// ---------------- K5: BN stats (deterministic, float4) ----------------
__global__ __launch_bounds__(256) void bn_stats()
{
    const int o = blockIdx.x;
    const int t = threadIdx.x;
    float s = 0.f, sq = 0.f;
#pragma unroll 4
    for (int k = 0; k < 32; k++) {
        int u = t + k * 256;
        int b = u >> 8, n4 = (u & 255) * 4;
        float4 v = *(const float4*)(g_P + ((size_t)b * C_ + o) * N_ + n4);
        s  += v.x + v.y + v.z + v.w;
        sq += v.x * v.x + v.y * v.y + v.z * v.z + v.w * v.w;
    }
    __shared__ float rs_[256], rq[256];
    rs_[t] = s; rq[t] = sq;
    __syncthreads();
    for (int st = 128; st > 0; st >>= 1) {
        if (t < st) { rs_[t] += rs_[t + st]; rq[t] += rq[t + st]; }
        __syncthreads();
    }
    if (t == 0) {
        float inv_n = 1.f / (float)(B_ * N_);
        float mu  = rs_[0] * inv_n;
        float var = rq[0] * inv_n - mu * mu;
        g_mean[o] = mu;
        g_rstd[o] = rsqrtf(var + EPS_);
    }
}

// ---------------- K6: residual + BN normalize (float4) ----------------
__global__ __launch_bounds__(256) void final_kernel(
    const float* __restrict__ x,
    const float* __restrict__ gamma,
    const float* __restrict__ beta,
    float* __restrict__ out)
{
    int idx = (blockIdx.x * 256 + threadIdx.x) * 4;
    int c = (idx / N_) % C_;
    float ga = gamma[c], be = beta[c], mu = g_mean[c], rs = g_rstd[c];
    float4 v = *(const float4*)(g_P + idx);
    float4 xv = *(const float4*)(x + idx);
    float4 r;
    r.x = xv.x + ga * (v.x - mu) * rs + be;
    r.y = xv.y + ga * (v.y - mu) * rs + be;
    r.z = xv.z + ga * (v.z - mu) * rs + be;
    r.w = xv.w + ga * (v.w - mu) * rs + be;
    *(float4*)(out + idx) = r;
}

// ---------------- launch ----------------
extern "C" void kernel_launch(void* const* d_in, const int* in_sizes, int n_in,
                              void* d_out, int out_size)
{
    const float* x     = (const float*)d_in[0];
    const float* Wq    = (const float*)d_in[1];
    const float* Wk    = (const float*)d_in[2];
    const float* Wv    = (const float*)d_in[3];
    const float* Wpe   = (const float*)d_in[4];
    const float* Wproj = (const float*)d_in[5];
    const float* gamma = (const float*)d_in[6];
    const float* beta  = (const float*)d_in[7];
    float* out = (float*)d_out;

    static bool attr_set = false;
    if (!attr_set) {
        cudaFuncSetAttribute(qkv_mma, cudaFuncAttributeMaxDynamicSharedMemorySize,
                             GS_FLOATS * (int)sizeof(float));
        cudaFuncSetAttribute(proj_mma, cudaFuncAttributeMaxDynamicSharedMemorySize,
                             PS_FLOATS * (int)sizeof(float));
        cudaFuncSetAttribute(attn_flash, cudaFuncAttributeMaxDynamicSharedMemorySize,
                             ATT_FLOATS * (int)sizeof(float));
        attr_set = true;
    }

    qkv_mma<<<dim3(N_ / 128, 9, B_), 256, GS_FLOATS * sizeof(float)>>>(Wq, Wk, Wv, x);

    attn_flash<<<dim3(4, NHEAD, 128), 256, ATT_FLOATS * sizeof(float)>>>(Wpe);

    proj_mma<<<dim3(N_ / 128, C_ / 128, B_), 256, PS_FLOATS * sizeof(float)>>>(Wproj);

    bn_stats<<<C_, 256>>>();

    final_kernel<<<(B_ * C_ * N_) / 1024, 256>>>(x, gamma, beta, out);
}

// round 8
// speedup vs baseline: 1.0523x; 1.0523x over previous
#include <cuda_runtime.h>
#include <math.h>
#include <stdint.h>

#define B_    32
#define C_    384
#define Hh    32
#define Ww    32
#define N_    1024
#define S_    4
#define NE    256
#define NHEAD 6
#define HD    64
#define EPS_  1e-5f

// ---------------- scratch (device globals; no allocation) ----------------
__device__ float g_Q [B_*C_*N_];   // [b][c][n]
__device__ float g_K [B_*C_*N_];
__device__ float g_V [B_*C_*N_];
__device__ float g_V2[B_*C_*N_];   // v + pe
__device__ float g_AO[B_*N_*C_];   // attention output [b][nf][cz]
__device__ float g_P [B_*C_*N_];   // proj output [b][c][n]
__device__ float g_mean[C_];
__device__ float g_rstd[C_];

// ---------------- generic-PTX helpers ----------------
__device__ __forceinline__ uint32_t smem_u32(const void* p) {
    uint32_t a;
    asm("{ .reg .u64 t; cvta.to.shared.u64 t, %1; cvt.u32.u64 %0, t; }" : "=r"(a) : "l"(p));
    return a;
}
__device__ __forceinline__ void cp16(uint32_t dst, const void* src) {
    asm volatile("cp.async.cg.shared.global [%0], [%1], 16;" :: "r"(dst), "l"(src) : "memory");
}
#define CP_COMMIT() asm volatile("cp.async.commit_group;" ::: "memory")
#define CP_WAIT(n)  asm volatile("cp.async.wait_group %0;" :: "n"(n) : "memory")

__device__ __forceinline__ uint32_t f2tf32(float f) {
    uint32_t u;
    asm("cvt.rna.tf32.f32 %0, %1;" : "=r"(u) : "f"(f));
    return u;
}
__device__ __forceinline__ float tf32f(float f) { return __uint_as_float(f2tf32(f)); }

__device__ __forceinline__ void mma_tf32(float c[4],
    uint32_t a0, uint32_t a1, uint32_t a2, uint32_t a3, uint32_t b0, uint32_t b1)
{
    asm volatile("mma.sync.aligned.m16n8k8.row.col.f32.tf32.tf32.f32 "
        "{%0,%1,%2,%3}, {%4,%5,%6,%7}, {%8,%9}, {%0,%1,%2,%3};"
        : "+f"(c[0]), "+f"(c[1]), "+f"(c[2]), "+f"(c[3])
        : "r"(a0), "r"(a1), "r"(a2), "r"(a3), "r"(b0), "r"(b1));
}

// k-pair permutation: {k, k+4} adjacent -> lds.64 A-frags
__device__ __forceinline__ int perm8(int r) { return (r < 4) ? (2 * r) : (2 * r - 7); }
__device__ __forceinline__ int pcol(int c) { return (c & ~7) | perm8(c & 7); }

// ---------------- K1: QKV tf32 GEMM (NN) — unchanged ----------------
#define A_STR 36
#define B_STR 136
#define A_CH  (128 * A_STR)
#define B_CH  (32 * B_STR)
#define A_TOT (2 * A_CH)
#define GS_FLOATS (A_TOT + 2 * B_CH)

__global__ __launch_bounds__(256) void qkv_mma(
    const float* __restrict__ Wq,
    const float* __restrict__ Wk,
    const float* __restrict__ Wv,
    const float* __restrict__ x)
{
    extern __shared__ float sm[];
    float* As = sm;
    float* Bs = sm + A_TOT;
    const uint32_t sb = smem_u32(sm);

    const int t   = threadIdx.x;
    const int wid = t >> 5;
    const int lane = t & 31;
    const int g  = lane >> 2;
    const int tg = lane & 3;
    const int wm = wid & 1;
    const int wn = wid >> 1;

    const int n0 = blockIdx.x * 128;
    const int y  = blockIdx.y;
    const int b  = blockIdx.z;

    const int fam = y / 3;
    const int o0 = (y % 3) * 128;
    const float* W = (fam == 0) ? Wq : (fam == 1) ? Wk : Wv;
    float* outbuf = (fam == 0) ? g_Q : (fam == 1) ? g_K : g_V;
    const float* Bp = x + (size_t)b * C_ * N_;

    float acc[4][4][4];
#pragma unroll
    for (int i = 0; i < 4; i++)
#pragma unroll
        for (int j = 0; j < 4; j++) {
            acc[i][j][0] = 0.f; acc[i][j][1] = 0.f;
            acc[i][j][2] = 0.f; acc[i][j][3] = 0.f;
        }

    auto issue = [&](int kc, int buf) {
        const int k0 = kc * 32;
        uint32_t adst = sb + (uint32_t)(buf * A_CH) * 4u;
        uint32_t bdst = sb + (uint32_t)(A_TOT + buf * B_CH) * 4u;
#pragma unroll
        for (int r = 0; r < 4; r++) {
            int i = t + r * 256;
            int row = i >> 3, c4 = (i & 7) * 4;
            cp16(adst + (uint32_t)(row * A_STR + c4) * 4u,
                 W + (size_t)(o0 + row) * C_ + k0 + c4);
        }
#pragma unroll
        for (int r = 0; r < 4; r++) {
            int i = t + r * 256;
            int row = i >> 5, c4 = (i & 31) * 4;
            cp16(bdst + (uint32_t)(row * B_STR + c4) * 4u,
                 Bp + (size_t)(k0 + row) * N_ + n0 + c4);
        }
    };

    issue(0, 0);
    CP_COMMIT();

    for (int kc = 0; kc < 12; kc++) {
        const int buf = kc & 1;
        if (kc + 1 < 12) {
            issue(kc + 1, buf ^ 1);
            CP_COMMIT();
            CP_WAIT(1);
        } else {
            CP_WAIT(0);
        }
        __syncthreads();

        const float* As_ = As + buf * A_CH;
        const float* Bs_ = Bs + buf * B_CH;

#pragma unroll
        for (int ks = 0; ks < 4; ks++) {
            const int k0 = ks * 8;
            uint32_t af[4][4], bf[4][2];
#pragma unroll
            for (int mt = 0; mt < 4; mt++) {
                const float* ap = As_ + (wm * 64 + mt * 16 + g) * A_STR + k0 + tg;
                af[mt][0] = f2tf32(ap[0]);
                af[mt][1] = f2tf32(ap[8 * A_STR]);
                af[mt][2] = f2tf32(ap[4]);
                af[mt][3] = f2tf32(ap[8 * A_STR + 4]);
            }
#pragma unroll
            for (int nt = 0; nt < 4; nt++) {
                const float* bp = Bs_ + (k0 + tg) * B_STR + wn * 32 + nt * 8 + g;
                bf[nt][0] = f2tf32(bp[0]);
                bf[nt][1] = f2tf32(bp[4 * B_STR]);
            }
#pragma unroll
            for (int mt = 0; mt < 4; mt++)
#pragma unroll
                for (int nt = 0; nt < 4; nt++)
                    mma_tf32(acc[mt][nt], af[mt][0], af[mt][1], af[mt][2], af[mt][3],
                             bf[nt][0], bf[nt][1]);
        }
        __syncthreads();
    }

    float* D = outbuf + (size_t)b * C_ * N_;
#pragma unroll
    for (int mt = 0; mt < 4; mt++) {
        const int o = o0 + wm * 64 + mt * 16 + g;
#pragma unroll
        for (int nt = 0; nt < 4; nt++) {
            const int n = n0 + wn * 32 + nt * 8 + tg * 2;
            *(float2*)(D + (size_t)o * N_ + n)       = make_float2(acc[mt][nt][0], acc[mt][nt][1]);
            *(float2*)(D + (size_t)(o + 8) * N_ + n) = make_float2(acc[mt][nt][2], acc[mt][nt][3]);
        }
    }
}

// ---------------- K4: proj tf32 GEMM (NT) — unchanged ----------------
#define P_CH (128 * A_STR)
#define PS_FLOATS (4 * P_CH)

__global__ __launch_bounds__(256) void proj_mma(const float* __restrict__ Wp)
{
    extern __shared__ float sm[];
    float* As = sm;
    float* Bs = sm + 2 * P_CH;
    const uint32_t sb = smem_u32(sm);

    const int t   = threadIdx.x;
    const int wid = t >> 5;
    const int lane = t & 31;
    const int g  = lane >> 2;
    const int tg = lane & 3;
    const int wm = wid & 1;
    const int wn = wid >> 1;

    const int n0 = blockIdx.x * 128;
    const int o0 = blockIdx.y * 128;
    const int b  = blockIdx.z;

    const float* Bp = g_AO + (size_t)b * N_ * C_;

    float acc[4][4][4];
#pragma unroll
    for (int i = 0; i < 4; i++)
#pragma unroll
        for (int j = 0; j < 4; j++) {
            acc[i][j][0] = 0.f; acc[i][j][1] = 0.f;
            acc[i][j][2] = 0.f; acc[i][j][3] = 0.f;
        }

    auto issue = [&](int kc, int buf) {
        const int k0 = kc * 32;
        uint32_t adst = sb + (uint32_t)(buf * P_CH) * 4u;
        uint32_t bdst = sb + (uint32_t)((2 + buf) * P_CH) * 4u;
#pragma unroll
        for (int r = 0; r < 4; r++) {
            int i = t + r * 256;
            int row = i >> 3, c4 = (i & 7) * 4;
            cp16(adst + (uint32_t)(row * A_STR + c4) * 4u,
                 Wp + (size_t)(o0 + row) * C_ + k0 + c4);
            cp16(bdst + (uint32_t)(row * A_STR + c4) * 4u,
                 Bp + (size_t)(n0 + row) * C_ + k0 + c4);
        }
    };

    issue(0, 0);
    CP_COMMIT();

    for (int kc = 0; kc < 12; kc++) {
        const int buf = kc & 1;
        if (kc + 1 < 12) {
            issue(kc + 1, buf ^ 1);
            CP_COMMIT();
            CP_WAIT(1);
        } else {
            CP_WAIT(0);
        }
        __syncthreads();

        const float* As_ = As + buf * P_CH;
        const float* Bs_ = Bs + buf * P_CH;

#pragma unroll
        for (int ks = 0; ks < 4; ks++) {
            const int k0 = ks * 8;
            uint32_t af[4][4], bf[4][2];
#pragma unroll
            for (int mt = 0; mt < 4; mt++) {
                const float* ap = As_ + (wm * 64 + mt * 16 + g) * A_STR + k0 + tg;
                af[mt][0] = f2tf32(ap[0]);
                af[mt][1] = f2tf32(ap[8 * A_STR]);
                af[mt][2] = f2tf32(ap[4]);
                af[mt][3] = f2tf32(ap[8 * A_STR + 4]);
            }
#pragma unroll
            for (int nt = 0; nt < 4; nt++) {
                const float* bp = Bs_ + (wn * 32 + nt * 8 + g) * A_STR + k0 + tg;
                bf[nt][0] = f2tf32(bp[0]);
                bf[nt][1] = f2tf32(bp[4]);
            }
#pragma unroll
            for (int mt = 0; mt < 4; mt++)
#pragma unroll
                for (int nt = 0; nt < 4; nt++)
                    mma_tf32(acc[mt][nt], af[mt][0], af[mt][1], af[mt][2], af[mt][3],
                             bf[nt][0], bf[nt][1]);
        }
        __syncthreads();
    }

    float* D = g_P + (size_t)b * C_ * N_;
#pragma unroll
    for (int mt = 0; mt < 4; mt++) {
        const int o = o0 + wm * 64 + mt * 16 + g;
#pragma unroll
        for (int nt = 0; nt < 4; nt++) {
            const int n = n0 + wn * 32 + nt * 8 + tg * 2;
            *(float2*)(D + (size_t)o * N_ + n)       = make_float2(acc[mt][nt][0], acc[mt][nt][1]);
            *(float2*)(D + (size_t)(o + 8) * N_ + n) = make_float2(acc[mt][nt][2], acc[mt][nt][3]);
        }
    }
}

// ---------------- K2: depthwise 3x3 PE + add (smem tiled, standalone) ----------------
__global__ __launch_bounds__(256) void dwconv_smem(const float* __restrict__ Wpe)
{
    __shared__ float tile[34 * 34];
    __shared__ float wsh[9];
    const int bc = blockIdx.x;
    const int c  = bc % C_;
    const float* vb = g_V + (size_t)bc * N_;
    const int t = threadIdx.x;
    if (t < 9) wsh[t] = Wpe[c * 9 + t];
    for (int i = t; i < 34 * 34; i += 256) {
        int r = i / 34 - 1, col = i % 34 - 1;
        tile[i] = (r >= 0 && r < 32 && col >= 0 && col < 32) ? vb[r * 32 + col] : 0.f;
    }
    __syncthreads();
    const float w0 = wsh[0], w1 = wsh[1], w2 = wsh[2];
    const float w3 = wsh[3], w4 = wsh[4], w5 = wsh[5];
    const float w6 = wsh[6], w7 = wsh[7], w8 = wsh[8];
    float* outp = g_V2 + (size_t)bc * N_;
#pragma unroll
    for (int j = 0; j < 4; j++) {
        int n = t + j * 256;
        int hh = n >> 5, ww = n & 31;
        const float* tp = &tile[hh * 34 + ww];
        float s = w0 * tp[0]  + w1 * tp[1]  + w2 * tp[2]
                + w3 * tp[34] + w4 * tp[35] + w5 * tp[36]
                + w6 * tp[68] + w7 * tp[69] + w8 * tp[70];
        outp[n] = tp[35] + s;
    }
}

// ---------------- K3: attention (tf32 mma.sync, 512 thr, pre-rounded K/V) ----------------
// One CTA per (h, be). 512 threads (16 warps). 4 passes of 64 Q-rows.
// smem floats:
//   Ks [64 d][264 m]  @ 0      (16896)  cp.async raw -> in-place tf32
//   Vs [64 d][260 m]  @ 16896  (16640)  cp.async raw -> in-place tf32
//   Qs [64 n][72 d]   @ 33536  (4608)   tf32-rounded + 0.125 scale, d pair-permuted
//   Sc [64 n][264 m]  @ 38144  (16896)  scores fp32 -> P tf32 (m pair-permuted)
#define KS_STR 264
#define VS_STR 260
#define QS_STR 72
#define SS_STR 264
#define OFF_KS 0
#define OFF_VS 16896
#define OFF_QS 33536
#define OFF_SC 38144
#define ATTN_FLOATS 55040   // 220160 bytes

__global__ __launch_bounds__(512, 1) void attn_mma()
{
    extern __shared__ float sm[];
    float* Ks = sm + OFF_KS;
    float* Vs = sm + OFF_VS;
    float* Qs = sm + OFF_QS;
    float* Sc = sm + OFF_SC;
    const uint32_t ks_b = smem_u32(Ks);
    const uint32_t vs_b = smem_u32(Vs);

    const int h  = blockIdx.x;      // 0..5
    const int be = blockIdx.y;      // 0..127
    const int b  = be >> 2;
    const int sP = be & 3;

    const int t = threadIdx.x;
    const int wid = t >> 5, lane = t & 31;
    const int g = lane >> 2, tg = lane & 3;
    const int wm = wid & 3;          // 4 row-tiles of 16
    const int wq = wid >> 2;         // 0..3: QK col quarter / AV d quarter

    const float* Qg = g_Q  + ((size_t)b * C_ + h * HD) * N_ + sP * NE;
    const float* Kg = g_K  + ((size_t)b * C_ + h * HD) * N_ + sP * NE;
    const float* Vg = g_V2 + ((size_t)b * C_ + h * HD) * N_ + sP * NE;

    // ---- cp.async load K, V (natural [d][m], coalesced) ----
#pragma unroll
    for (int j = 0; j < 8; j++) {
        int u = t + j * 512;                 // 4096 float4 units
        int d = u >> 6, m4 = (u & 63) * 4;
        cp16(ks_b + (uint32_t)(d * KS_STR + m4) * 4u, Kg + (size_t)d * N_ + m4);
    }
#pragma unroll
    for (int j = 0; j < 8; j++) {
        int u = t + j * 512;
        int d = u >> 6, m4 = (u & 63) * 4;
        cp16(vs_b + (uint32_t)(d * VS_STR + m4) * 4u, Vg + (size_t)d * N_ + m4);
    }
    CP_COMMIT();
    CP_WAIT(0);
    __syncthreads();

    // ---- in-place tf32 round of K and V (data cols only) ----
#pragma unroll
    for (int j = 0; j < 8; j++) {
        int u = t + j * 512;                 // 4096 units
        int d = u >> 6, m4 = (u & 63) * 4;
        float4* p = (float4*)&Ks[d * KS_STR + m4];
        float4 v = *p;
        v.x = tf32f(v.x); v.y = tf32f(v.y); v.z = tf32f(v.z); v.w = tf32f(v.w);
        *p = v;
        float4* q = (float4*)&Vs[d * VS_STR + m4];
        float4 w = *q;
        w.x = tf32f(w.x); w.y = tf32f(w.y); w.z = tf32f(w.z); w.w = tf32f(w.w);
        *q = w;
    }

    const int c0p = perm8(2 * tg), c1p = perm8(2 * tg + 1);
    float* AOb = g_AO + (size_t)b * N_ * C_;

    for (int pass = 0; pass < 4; pass++) {
        const int n0 = pass * 64;

        // ---- Q transform: [d][n] -> Qs[n][pcol(d)], 0.125-scaled, tf32 ----
#pragma unroll
        for (int j = 0; j < 2; j++) {
            int u = t + j * 512;             // 1024 units: 64 d x 16 n4
            int d = u >> 4, n4 = (u & 15) * 4;
            float4 v = *(const float4*)(Qg + (size_t)d * N_ + n0 + n4);
            int pd = pcol(d);
            Qs[(n4 + 0) * QS_STR + pd] = tf32f(0.125f * v.x);
            Qs[(n4 + 1) * QS_STR + pd] = tf32f(0.125f * v.y);
            Qs[(n4 + 2) * QS_STR + pd] = tf32f(0.125f * v.z);
            Qs[(n4 + 3) * QS_STR + pd] = tf32f(0.125f * v.w);
        }
        __syncthreads();   // Qs + (pass0: cvt) ready; prior-pass Sc reads done

        // ---- QK^T: each warp 16 rows x 64 cols (3 instr / MMA) ----
        float acc[8][4];
#pragma unroll
        for (int i = 0; i < 8; i++) {
            acc[i][0] = 0.f; acc[i][1] = 0.f; acc[i][2] = 0.f; acc[i][3] = 0.f;
        }
#pragma unroll
        for (int ks = 0; ks < 8; ks++) {
            const float* ap = Qs + (wm * 16 + g) * QS_STR + ks * 8 + 2 * tg;
            float2 aL = *(const float2*)ap;
            float2 aH = *(const float2*)(ap + 8 * QS_STR);
            uint32_t a0 = __float_as_uint(aL.x), a2 = __float_as_uint(aL.y);
            uint32_t a1 = __float_as_uint(aH.x), a3 = __float_as_uint(aH.y);
#pragma unroll
            for (int nf = 0; nf < 8; nf++) {
                const float* bp = Ks + (ks * 8 + tg) * KS_STR + wq * 64 + nf * 8 + g;
                mma_tf32(acc[nf], a0, a1, a2, a3,
                         __float_as_uint(bp[0]), __float_as_uint(bp[4 * KS_STR]));
            }
        }
        {
            const int r0 = wm * 16 + g;
#pragma unroll
            for (int nf = 0; nf < 8; nf++) {
                const int mb = wq * 64 + nf * 8;
                Sc[r0 * SS_STR + mb + c0p]       = acc[nf][0];
                Sc[r0 * SS_STR + mb + c1p]       = acc[nf][1];
                Sc[(r0 + 8) * SS_STR + mb + c0p] = acc[nf][2];
                Sc[(r0 + 8) * SS_STR + mb + c1p] = acc[nf][3];
            }
        }
        __syncthreads();

        // ---- softmax (warp per 4 rows); write P as tf32 in-place ----
        {
#pragma unroll
            for (int rr = 0; rr < 4; rr++) {
                int r = wid * 4 + rr;
                float* row = &Sc[r * SS_STR];
                float vals[8];
                float mx = -1e30f;
#pragma unroll
                for (int j = 0; j < 8; j++) {
                    vals[j] = row[lane + 32 * j];
                    mx = fmaxf(mx, vals[j]);
                }
#pragma unroll
                for (int o = 16; o > 0; o >>= 1)
                    mx = fmaxf(mx, __shfl_xor_sync(0xffffffffu, mx, o));
                float sum = 0.f;
#pragma unroll
                for (int j = 0; j < 8; j++) {
                    vals[j] = __expf(vals[j] - mx);
                    sum += vals[j];
                }
#pragma unroll
                for (int o = 16; o > 0; o >>= 1)
                    sum += __shfl_xor_sync(0xffffffffu, sum, o);
                float inv = 1.f / sum;
#pragma unroll
                for (int j = 0; j < 8; j++)
                    row[lane + 32 * j] = tf32f(vals[j] * inv);
            }
        }
        __syncthreads();

        // ---- AV: each warp 16 rows x 16 d (3 instr / MMA) ----
        float av[2][4];
        av[0][0] = av[0][1] = av[0][2] = av[0][3] = 0.f;
        av[1][0] = av[1][1] = av[1][2] = av[1][3] = 0.f;
#pragma unroll
        for (int ks = 0; ks < 32; ks++) {
            const float* ap = Sc + (wm * 16 + g) * SS_STR + ks * 8 + 2 * tg;
            float2 aL = *(const float2*)ap;
            float2 aH = *(const float2*)(ap + 8 * SS_STR);
            uint32_t a0 = __float_as_uint(aL.x), a2 = __float_as_uint(aL.y);
            uint32_t a1 = __float_as_uint(aH.x), a3 = __float_as_uint(aH.y);
#pragma unroll
            for (int nf = 0; nf < 2; nf++) {
                const float* bp = Vs + (wq * 16 + nf * 8 + g) * VS_STR + ks * 8 + tg;
                mma_tf32(av[nf], a0, a1, a2, a3,
                         __float_as_uint(bp[0]), __float_as_uint(bp[4]));
            }
        }

        // ---- store to AO[b][nf2][cz] ----
#pragma unroll
        for (int nf = 0; nf < 2; nf++) {
#pragma unroll
            for (int e = 0; e < 4; e++) {
                int n = n0 + wm * 16 + g + ((e >> 1) ? 8 : 0);
                int d = wq * 16 + nf * 8 + 2 * tg + (e & 1);
                unsigned lin = (unsigned)(h * HD + d) * NE + (unsigned)n;
                unsigned ne2 = lin / C_;
                unsigned cz  = lin - ne2 * C_;
                unsigned nf2 = ne2 * S_ + (unsigned)sP;
                AOb[(size_t)nf2 * C_ + cz] = av[nf][e];
            }
        }
    }
}

// ---------------- K5: BN stats (deterministic, float4) ----------------
__global__ __launch_bounds__(256) void bn_stats()
{
    const int o = blockIdx.x;
    const int t = threadIdx.x;
    float s = 0.f, sq = 0.f;
#pragma unroll 4
    for (int k = 0; k < 32; k++) {
        int u = t + k * 256;
        int b = u >> 8, n4 = (u & 255) * 4;
        float4 v = *(const float4*)(g_P + ((size_t)b * C_ + o) * N_ + n4);
        s  += v.x + v.y + v.z + v.w;
        sq += v.x * v.x + v.y * v.y + v.z * v.z + v.w * v.w;
    }
    __shared__ float rs_[256], rq[256];
    rs_[t] = s; rq[t] = sq;
    __syncthreads();
    for (int st = 128; st > 0; st >>= 1) {
        if (t < st) { rs_[t] += rs_[t + st]; rq[t] += rq[t + st]; }
        __syncthreads();
    }
    if (t == 0) {
        float inv_n = 1.f / (float)(B_ * N_);
        float mu  = rs_[0] * inv_n;
        float var = rq[0] * inv_n - mu * mu;
        g_mean[o] = mu;
        g_rstd[o] = rsqrtf(var + EPS_);
    }
}

// ---------------- K6: residual + BN normalize (float4) ----------------
__global__ __launch_bounds__(256) void final_kernel(
    const float* __restrict__ x,
    const float* __restrict__ gamma,
    const float* __restrict__ beta,
    float* __restrict__ out)
{
    int idx = (blockIdx.x * 256 + threadIdx.x) * 4;
    int c = (idx / N_) % C_;
    float ga = gamma[c], be = beta[c], mu = g_mean[c], rs = g_rstd[c];
    float4 v = *(const float4*)(g_P + idx);
    float4 xv = *(const float4*)(x + idx);
    float4 r;
    r.x = xv.x + ga * (v.x - mu) * rs + be;
    r.y = xv.y + ga * (v.y - mu) * rs + be;
    r.z = xv.z + ga * (v.z - mu) * rs + be;
    r.w = xv.w + ga * (v.w - mu) * rs + be;
    *(float4*)(out + idx) = r;
}

// ---------------- launch ----------------
extern "C" void kernel_launch(void* const* d_in, const int* in_sizes, int n_in,
                              void* d_out, int out_size)
{
    const float* x     = (const float*)d_in[0];
    const float* Wq    = (const float*)d_in[1];
    const float* Wk    = (const float*)d_in[2];
    const float* Wv    = (const float*)d_in[3];
    const float* Wpe   = (const float*)d_in[4];
    const float* Wproj = (const float*)d_in[5];
    const float* gamma = (const float*)d_in[6];
    const float* beta  = (const float*)d_in[7];
    float* out = (float*)d_out;

    static bool attr_set = false;
    if (!attr_set) {
        cudaFuncSetAttribute(qkv_mma, cudaFuncAttributeMaxDynamicSharedMemorySize,
                             GS_FLOATS * (int)sizeof(float));
        cudaFuncSetAttribute(proj_mma, cudaFuncAttributeMaxDynamicSharedMemorySize,
                             PS_FLOATS * (int)sizeof(float));
        cudaFuncSetAttribute(attn_mma, cudaFuncAttributeMaxDynamicSharedMemorySize,
                             ATTN_FLOATS * (int)sizeof(float));
        attr_set = true;
    }

    qkv_mma<<<dim3(N_ / 128, 9, B_), 256, GS_FLOATS * sizeof(float)>>>(Wq, Wk, Wv, x);

    dwconv_smem<<<B_ * C_, 256>>>(Wpe);

    attn_mma<<<dim3(NHEAD, 128), 512, ATTN_FLOATS * sizeof(float)>>>();

    proj_mma<<<dim3(N_ / 128, C_ / 128, B_), 256, PS_FLOATS * sizeof(float)>>>(Wproj);

    bn_stats<<<C_, 256>>>();

    final_kernel<<<(B_ * C_ * N_) / 1024, 256>>>(x, gamma, beta, out);
}

// round 9
// speedup vs baseline: 1.1977x; 1.1381x over previous
#include <cuda_runtime.h>
#include <math.h>
#include <stdint.h>

#define B_    32
#define C_    384
#define Hh    32
#define Ww    32
#define N_    1024
#define S_    4
#define NE    256
#define NHEAD 6
#define HD    64
#define EPS_  1e-5f

// ---------------- scratch (device globals; no allocation) ----------------
__device__ float g_Q [B_*C_*N_];   // [b][c][n]
__device__ float g_K [B_*C_*N_];
__device__ float g_V [B_*C_*N_];
__device__ float g_V2[B_*C_*N_];   // v + pe
__device__ float g_AO[B_*N_*C_];   // attention output [b][nf][cz]
__device__ float g_P [B_*C_*N_];   // proj output [b][c][n]
__device__ float g_mean[C_];
__device__ float g_rstd[C_];

// ---------------- generic-PTX helpers ----------------
__device__ __forceinline__ uint32_t smem_u32(const void* p) {
    uint32_t a;
    asm("{ .reg .u64 t; cvta.to.shared.u64 t, %1; cvt.u32.u64 %0, t; }" : "=r"(a) : "l"(p));
    return a;
}
__device__ __forceinline__ void cp16(uint32_t dst, const void* src) {
    asm volatile("cp.async.cg.shared.global [%0], [%1], 16;" :: "r"(dst), "l"(src) : "memory");
}
#define CP_COMMIT() asm volatile("cp.async.commit_group;" ::: "memory")
#define CP_WAIT(n)  asm volatile("cp.async.wait_group %0;" :: "n"(n) : "memory")

__device__ __forceinline__ uint32_t f2tf32(float f) {
    uint32_t u;
    asm("cvt.rna.tf32.f32 %0, %1;" : "=r"(u) : "f"(f));
    return u;
}
__device__ __forceinline__ float tf32f(float f) { return __uint_as_float(f2tf32(f)); }

__device__ __forceinline__ void mma_tf32(float c[4],
    uint32_t a0, uint32_t a1, uint32_t a2, uint32_t a3, uint32_t b0, uint32_t b1)
{
    asm volatile("mma.sync.aligned.m16n8k8.row.col.f32.tf32.tf32.f32 "
        "{%0,%1,%2,%3}, {%4,%5,%6,%7}, {%8,%9}, {%0,%1,%2,%3};"
        : "+f"(c[0]), "+f"(c[1]), "+f"(c[2]), "+f"(c[3])
        : "r"(a0), "r"(a1), "r"(a2), "r"(a3), "r"(b0), "r"(b1));
}

// ---------------- K1: QKV tf32 GEMM (NN) — unchanged ----------------
#define A_STR 36
#define B_STR 136
#define A_CH  (128 * A_STR)
#define B_CH  (32 * B_STR)
#define A_TOT (2 * A_CH)
#define GS_FLOATS (A_TOT + 2 * B_CH)

__global__ __launch_bounds__(256) void qkv_mma(
    const float* __restrict__ Wq,
    const float* __restrict__ Wk,
    const float* __restrict__ Wv,
    const float* __restrict__ x)
{
    extern __shared__ float sm[];
    float* As = sm;
    float* Bs = sm + A_TOT;
    const uint32_t sb = smem_u32(sm);

    const int t   = threadIdx.x;
    const int wid = t >> 5;
    const int lane = t & 31;
    const int g  = lane >> 2;
    const int tg = lane & 3;
    const int wm = wid & 1;
    const int wn = wid >> 1;

    const int n0 = blockIdx.x * 128;
    const int y  = blockIdx.y;
    const int b  = blockIdx.z;

    const int fam = y / 3;
    const int o0 = (y % 3) * 128;
    const float* W = (fam == 0) ? Wq : (fam == 1) ? Wk : Wv;
    float* outbuf = (fam == 0) ? g_Q : (fam == 1) ? g_K : g_V;
    const float* Bp = x + (size_t)b * C_ * N_;

    float acc[4][4][4];
#pragma unroll
    for (int i = 0; i < 4; i++)
#pragma unroll
        for (int j = 0; j < 4; j++) {
            acc[i][j][0] = 0.f; acc[i][j][1] = 0.f;
            acc[i][j][2] = 0.f; acc[i][j][3] = 0.f;
        }

    auto issue = [&](int kc, int buf) {
        const int k0 = kc * 32;
        uint32_t adst = sb + (uint32_t)(buf * A_CH) * 4u;
        uint32_t bdst = sb + (uint32_t)(A_TOT + buf * B_CH) * 4u;
#pragma unroll
        for (int r = 0; r < 4; r++) {
            int i = t + r * 256;
            int row = i >> 3, c4 = (i & 7) * 4;
            cp16(adst + (uint32_t)(row * A_STR + c4) * 4u,
                 W + (size_t)(o0 + row) * C_ + k0 + c4);
        }
#pragma unroll
        for (int r = 0; r < 4; r++) {
            int i = t + r * 256;
            int row = i >> 5, c4 = (i & 31) * 4;
            cp16(bdst + (uint32_t)(row * B_STR + c4) * 4u,
                 Bp + (size_t)(k0 + row) * N_ + n0 + c4);
        }
    };

    issue(0, 0);
    CP_COMMIT();

    for (int kc = 0; kc < 12; kc++) {
        const int buf = kc & 1;
        if (kc + 1 < 12) {
            issue(kc + 1, buf ^ 1);
            CP_COMMIT();
            CP_WAIT(1);
        } else {
            CP_WAIT(0);
        }
        __syncthreads();

        const float* As_ = As + buf * A_CH;
        const float* Bs_ = Bs + buf * B_CH;

#pragma unroll
        for (int ks = 0; ks < 4; ks++) {
            const int k0 = ks * 8;
            uint32_t af[4][4], bf[4][2];
#pragma unroll
            for (int mt = 0; mt < 4; mt++) {
                const float* ap = As_ + (wm * 64 + mt * 16 + g) * A_STR + k0 + tg;
                af[mt][0] = f2tf32(ap[0]);
                af[mt][1] = f2tf32(ap[8 * A_STR]);
                af[mt][2] = f2tf32(ap[4]);
                af[mt][3] = f2tf32(ap[8 * A_STR + 4]);
            }
#pragma unroll
            for (int nt = 0; nt < 4; nt++) {
                const float* bp = Bs_ + (k0 + tg) * B_STR + wn * 32 + nt * 8 + g;
                bf[nt][0] = f2tf32(bp[0]);
                bf[nt][1] = f2tf32(bp[4 * B_STR]);
            }
#pragma unroll
            for (int mt = 0; mt < 4; mt++)
#pragma unroll
                for (int nt = 0; nt < 4; nt++)
                    mma_tf32(acc[mt][nt], af[mt][0], af[mt][1], af[mt][2], af[mt][3],
                             bf[nt][0], bf[nt][1]);
        }
        __syncthreads();
    }

    float* D = outbuf + (size_t)b * C_ * N_;
#pragma unroll
    for (int mt = 0; mt < 4; mt++) {
        const int o = o0 + wm * 64 + mt * 16 + g;
#pragma unroll
        for (int nt = 0; nt < 4; nt++) {
            const int n = n0 + wn * 32 + nt * 8 + tg * 2;
            *(float2*)(D + (size_t)o * N_ + n)       = make_float2(acc[mt][nt][0], acc[mt][nt][1]);
            *(float2*)(D + (size_t)(o + 8) * N_ + n) = make_float2(acc[mt][nt][2], acc[mt][nt][3]);
        }
    }
}

// ---------------- K4: proj tf32 GEMM (NT) — unchanged ----------------
#define P_CH (128 * A_STR)
#define PS_FLOATS (4 * P_CH)

__global__ __launch_bounds__(256) void proj_mma(const float* __restrict__ Wp)
{
    extern __shared__ float sm[];
    float* As = sm;
    float* Bs = sm + 2 * P_CH;
    const uint32_t sb = smem_u32(sm);

    const int t   = threadIdx.x;
    const int wid = t >> 5;
    const int lane = t & 31;
    const int g  = lane >> 2;
    const int tg = lane & 3;
    const int wm = wid & 1;
    const int wn = wid >> 1;

    const int n0 = blockIdx.x * 128;
    const int o0 = blockIdx.y * 128;
    const int b  = blockIdx.z;

    const float* Bp = g_AO + (size_t)b * N_ * C_;

    float acc[4][4][4];
#pragma unroll
    for (int i = 0; i < 4; i++)
#pragma unroll
        for (int j = 0; j < 4; j++) {
            acc[i][j][0] = 0.f; acc[i][j][1] = 0.f;
            acc[i][j][2] = 0.f; acc[i][j][3] = 0.f;
        }

    auto issue = [&](int kc, int buf) {
        const int k0 = kc * 32;
        uint32_t adst = sb + (uint32_t)(buf * P_CH) * 4u;
        uint32_t bdst = sb + (uint32_t)((2 + buf) * P_CH) * 4u;
#pragma unroll
        for (int r = 0; r < 4; r++) {
            int i = t + r * 256;
            int row = i >> 3, c4 = (i & 7) * 4;
            cp16(adst + (uint32_t)(row * A_STR + c4) * 4u,
                 Wp + (size_t)(o0 + row) * C_ + k0 + c4);
            cp16(bdst + (uint32_t)(row * A_STR + c4) * 4u,
                 Bp + (size_t)(n0 + row) * C_ + k0 + c4);
        }
    };

    issue(0, 0);
    CP_COMMIT();

    for (int kc = 0; kc < 12; kc++) {
        const int buf = kc & 1;
        if (kc + 1 < 12) {
            issue(kc + 1, buf ^ 1);
            CP_COMMIT();
            CP_WAIT(1);
        } else {
            CP_WAIT(0);
        }
        __syncthreads();

        const float* As_ = As + buf * P_CH;
        const float* Bs_ = Bs + buf * P_CH;

#pragma unroll
        for (int ks = 0; ks < 4; ks++) {
            const int k0 = ks * 8;
            uint32_t af[4][4], bf[4][2];
#pragma unroll
            for (int mt = 0; mt < 4; mt++) {
                const float* ap = As_ + (wm * 64 + mt * 16 + g) * A_STR + k0 + tg;
                af[mt][0] = f2tf32(ap[0]);
                af[mt][1] = f2tf32(ap[8 * A_STR]);
                af[mt][2] = f2tf32(ap[4]);
                af[mt][3] = f2tf32(ap[8 * A_STR + 4]);
            }
#pragma unroll
            for (int nt = 0; nt < 4; nt++) {
                const float* bp = Bs_ + (wn * 32 + nt * 8 + g) * A_STR + k0 + tg;
                bf[nt][0] = f2tf32(bp[0]);
                bf[nt][1] = f2tf32(bp[4]);
            }
#pragma unroll
            for (int mt = 0; mt < 4; mt++)
#pragma unroll
                for (int nt = 0; nt < 4; nt++)
                    mma_tf32(acc[mt][nt], af[mt][0], af[mt][1], af[mt][2], af[mt][3],
                             bf[nt][0], bf[nt][1]);
        }
        __syncthreads();
    }

    float* D = g_P + (size_t)b * C_ * N_;
#pragma unroll
    for (int mt = 0; mt < 4; mt++) {
        const int o = o0 + wm * 64 + mt * 16 + g;
#pragma unroll
        for (int nt = 0; nt < 4; nt++) {
            const int n = n0 + wn * 32 + nt * 8 + tg * 2;
            *(float2*)(D + (size_t)o * N_ + n)       = make_float2(acc[mt][nt][0], acc[mt][nt][1]);
            *(float2*)(D + (size_t)(o + 8) * N_ + n) = make_float2(acc[mt][nt][2], acc[mt][nt][3]);
        }
    }
}

// ---------------- K2: depthwise 3x3 PE + add (smem tiled) ----------------
__global__ __launch_bounds__(256) void dwconv_smem(const float* __restrict__ Wpe)
{
    __shared__ float tile[34 * 34];
    __shared__ float wsh[9];
    const int bc = blockIdx.x;
    const int c  = bc % C_;
    const float* vb = g_V + (size_t)bc * N_;
    const int t = threadIdx.x;
    if (t < 9) wsh[t] = Wpe[c * 9 + t];
    for (int i = t; i < 34 * 34; i += 256) {
        int r = i / 34 - 1, col = i % 34 - 1;
        tile[i] = (r >= 0 && r < 32 && col >= 0 && col < 32) ? vb[r * 32 + col] : 0.f;
    }
    __syncthreads();
    const float w0 = wsh[0], w1 = wsh[1], w2 = wsh[2];
    const float w3 = wsh[3], w4 = wsh[4], w5 = wsh[5];
    const float w6 = wsh[6], w7 = wsh[7], w8 = wsh[8];
    float* outp = g_V2 + (size_t)bc * N_;
#pragma unroll
    for (int j = 0; j < 4; j++) {
        int n = t + j * 256;
        int hh = n >> 5, ww = n & 31;
        const float* tp = &tile[hh * 34 + ww];
        float s = w0 * tp[0]  + w1 * tp[1]  + w2 * tp[2]
                + w3 * tp[34] + w4 * tp[35] + w5 * tp[36]
                + w6 * tp[68] + w7 * tp[69] + w8 * tp[70];
        outp[n] = tp[35] + s;
    }
}

// ---------------- K3: attention — FA2, occ 2, cp.async V2, pre-rounded K/V ----------------
// Grid (4 nt, 6 h, 128 be). 256 threads (8 warps: wm rows, wh m-half of chunk).
// 2 m-chunks of 128; Q + P + AV acc in registers; online softmax.
// smem floats: Ks[64][136]=8704, Vs[64][136]=8704, rm[64], rs[64],
//              redmax[128], redsum[128]  -> 17792 floats = 71168 B (occ 2)
#define KS2 136
#define VS2 136
#define F_KS 0
#define F_VS 8704
#define F_RM 17408
#define F_RS 17472
#define F_MX 17536
#define F_SM 17664
#define ATT_FLOATS 17792

__global__ __launch_bounds__(256, 2) void attn_flash()
{
    extern __shared__ float sm[];
    float* Ks     = sm + F_KS;
    float* Vs     = sm + F_VS;
    float* rm     = sm + F_RM;
    float* rs     = sm + F_RS;
    float* redmax = sm + F_MX;
    float* redsum = sm + F_SM;
    float* exch   = Ks;               // overlay: Ks dead after last QK
    const uint32_t ks_b = smem_u32(Ks);
    const uint32_t vs_b = smem_u32(Vs);

    const int nt = blockIdx.x;        // 0..3 : 64-row Q block
    const int h  = blockIdx.y;        // 0..5
    const int be = blockIdx.z;        // 0..127
    const int b  = be >> 2;
    const int sP = be & 3;
    const int n0 = nt * 64;

    const int t = threadIdx.x;
    const int wid = t >> 5, lane = t & 31;
    const int g = lane >> 2, tg = lane & 3;
    const int wm = wid & 3;           // row tile (16 rows)
    const int wh = wid >> 2;          // m-half of chunk (64 cols)

    const float* Qg = g_Q  + ((size_t)b * C_ + h * HD) * N_ + sP * NE;
    const float* Kg = g_K  + ((size_t)b * C_ + h * HD) * N_ + sP * NE;
    const float* Vg = g_V2 + ((size_t)b * C_ + h * HD) * N_ + sP * NE;

    // ---- Q -> registers (scaled by 1/8, tf32) ----
    uint32_t qa[8][4];
#pragma unroll
    for (int ks = 0; ks < 8; ks++) {
        int d0 = ks * 8 + tg, d1 = d0 + 4;
        int c0 = n0 + wm * 16 + g;
        qa[ks][0] = f2tf32(0.125f * Qg[(size_t)d0 * N_ + c0]);
        qa[ks][1] = f2tf32(0.125f * Qg[(size_t)d0 * N_ + c0 + 8]);
        qa[ks][2] = f2tf32(0.125f * Qg[(size_t)d1 * N_ + c0]);
        qa[ks][3] = f2tf32(0.125f * Qg[(size_t)d1 * N_ + c0 + 8]);
    }

    if (t < 64) { rm[t] = -1e30f; rs[t] = 0.f; }

    const int r1 = wm * 16 + g;
    const int r2 = r1 + 8;

    float av[8][4];
#pragma unroll
    for (int i = 0; i < 8; i++) {
        av[i][0] = 0.f; av[i][1] = 0.f; av[i][2] = 0.f; av[i][3] = 0.f;
    }

    for (int ck = 0; ck < 2; ck++) {
        __syncthreads();   // smem buffers free + (first iter) rm/rs ready

        // ---- K/V chunk via cp.async (coalesced) ----
#pragma unroll
        for (int j = 0; j < 8; j++) {
            int u = t + j * 256;            // 2048 float4 units: 64 d x 32 m4
            int d = u >> 5, m4 = (u & 31) * 4;
            cp16(ks_b + (uint32_t)(d * KS2 + m4) * 4u,
                 Kg + (size_t)d * N_ + ck * 128 + m4);
        }
#pragma unroll
        for (int j = 0; j < 8; j++) {
            int u = t + j * 256;
            int d = u >> 5, m4 = (u & 31) * 4;
            cp16(vs_b + (uint32_t)(d * VS2 + m4) * 4u,
                 Vg + (size_t)d * N_ + ck * 128 + m4);
        }
        CP_COMMIT();
        CP_WAIT(0);
        __syncthreads();

        // ---- in-place tf32 round of K and V ----
#pragma unroll
        for (int j = 0; j < 8; j++) {
            int u = t + j * 256;
            int d = u >> 5, m4 = (u & 31) * 4;
            float4* p = (float4*)&Ks[d * KS2 + m4];
            float4 v = *p;
            v.x = tf32f(v.x); v.y = tf32f(v.y); v.z = tf32f(v.z); v.w = tf32f(v.w);
            *p = v;
            float4* q = (float4*)&Vs[d * VS2 + m4];
            float4 w = *q;
            w.x = tf32f(w.x); w.y = tf32f(w.y); w.z = tf32f(w.z); w.w = tf32f(w.w);
            *q = w;
        }
        __syncthreads();

        // ---- QK^T: acc[8 nf][4] over warp's 64 m-cols (2 LDS + MMA) ----
        float acc[8][4];
#pragma unroll
        for (int i = 0; i < 8; i++) {
            acc[i][0] = 0.f; acc[i][1] = 0.f; acc[i][2] = 0.f; acc[i][3] = 0.f;
        }
#pragma unroll
        for (int ks = 0; ks < 8; ks++) {
#pragma unroll
            for (int nf = 0; nf < 8; nf++) {
                const float* bp = Ks + (ks * 8 + tg) * KS2 + wh * 64 + nf * 8 + g;
                mma_tf32(acc[nf], qa[ks][0], qa[ks][1], qa[ks][2], qa[ks][3],
                         __float_as_uint(bp[0]), __float_as_uint(bp[4 * KS2]));
            }
        }

        // ---- online softmax (rows r1, r2) ----
        float m1 = -1e30f, m2 = -1e30f;
#pragma unroll
        for (int nf = 0; nf < 8; nf++) {
            m1 = fmaxf(m1, fmaxf(acc[nf][0], acc[nf][1]));
            m2 = fmaxf(m2, fmaxf(acc[nf][2], acc[nf][3]));
        }
        m1 = fmaxf(m1, __shfl_xor_sync(0xffffffffu, m1, 1));
        m1 = fmaxf(m1, __shfl_xor_sync(0xffffffffu, m1, 2));
        m2 = fmaxf(m2, __shfl_xor_sync(0xffffffffu, m2, 1));
        m2 = fmaxf(m2, __shfl_xor_sync(0xffffffffu, m2, 2));
        if (tg == 0) { redmax[r1 * 2 + wh] = m1; redmax[r2 * 2 + wh] = m2; }
        __syncthreads();

        float nm1 = fmaxf(rm[r1], fmaxf(redmax[r1 * 2], redmax[r1 * 2 + 1]));
        float nm2 = fmaxf(rm[r2], fmaxf(redmax[r2 * 2], redmax[r2 * 2 + 1]));
        float corr1 = __expf(rm[r1] - nm1);
        float corr2 = __expf(rm[r2] - nm2);

        float s1 = 0.f, s2 = 0.f;
#pragma unroll
        for (int nf = 0; nf < 8; nf++) {
            acc[nf][0] = __expf(acc[nf][0] - nm1);
            acc[nf][1] = __expf(acc[nf][1] - nm1);
            acc[nf][2] = __expf(acc[nf][2] - nm2);
            acc[nf][3] = __expf(acc[nf][3] - nm2);
            s1 += acc[nf][0] + acc[nf][1];
            s2 += acc[nf][2] + acc[nf][3];
        }
        s1 += __shfl_xor_sync(0xffffffffu, s1, 1);
        s1 += __shfl_xor_sync(0xffffffffu, s1, 2);
        s2 += __shfl_xor_sync(0xffffffffu, s2, 1);
        s2 += __shfl_xor_sync(0xffffffffu, s2, 2);
        if (tg == 0) { redsum[r1 * 2 + wh] = s1; redsum[r2 * 2 + wh] = s2; }

        // rescale output accumulators
#pragma unroll
        for (int nf = 0; nf < 8; nf++) {
            av[nf][0] *= corr1; av[nf][1] *= corr1;
            av[nf][2] *= corr2; av[nf][3] *= corr2;
        }
        __syncthreads();

        if (wh == 0 && tg == 0) {
            rs[r1] = rs[r1] * corr1 + redsum[r1 * 2] + redsum[r1 * 2 + 1];
            rs[r2] = rs[r2] * corr2 + redsum[r2 * 2] + redsum[r2 * 2 + 1];
            rm[r1] = nm1;
            rm[r2] = nm2;
        }

        // ---- AV: av += P (regs) x V (smem), warp's m-half (1 LDS.64 + MMA) ----
#pragma unroll
        for (int ks2 = 0; ks2 < 8; ks2++) {
            uint32_t a0 = f2tf32(acc[ks2][0]);
            uint32_t a1 = f2tf32(acc[ks2][2]);
            uint32_t a2 = f2tf32(acc[ks2][1]);
            uint32_t a3 = f2tf32(acc[ks2][3]);
#pragma unroll
            for (int nf2 = 0; nf2 < 8; nf2++) {
                const float2 bv = *(const float2*)(Vs + (nf2 * 8 + g) * VS2
                                                   + wh * 64 + ks2 * 8 + 2 * tg);
                mma_tf32(av[nf2], a0, a1, a2, a3,
                         __float_as_uint(bv.x), __float_as_uint(bv.y));
            }
        }
    }

    // ---- cross-half reduction + normalize + store ----
    __syncthreads();    // Ks (exch overlay) fully dead; rs final visible
    if (wh == 1) {
#pragma unroll
        for (int nf2 = 0; nf2 < 8; nf2++) {
            exch[r1 * 72 + nf2 * 8 + 2 * tg]     = av[nf2][0];
            exch[r1 * 72 + nf2 * 8 + 2 * tg + 1] = av[nf2][1];
            exch[r2 * 72 + nf2 * 8 + 2 * tg]     = av[nf2][2];
            exch[r2 * 72 + nf2 * 8 + 2 * tg + 1] = av[nf2][3];
        }
    }
    __syncthreads();
    if (wh == 0) {
        float inv1 = 1.f / rs[r1];
        float inv2 = 1.f / rs[r2];
        float* AOb = g_AO + (size_t)b * N_ * C_;
#pragma unroll
        for (int nf2 = 0; nf2 < 8; nf2++) {
#pragma unroll
            for (int e = 0; e < 4; e++) {
                int d = nf2 * 8 + 2 * tg + (e & 1);
                int rr = (e >> 1) ? r2 : r1;
                float v = (av[nf2][e] + exch[rr * 72 + d]) * ((e >> 1) ? inv2 : inv1);
                int n = n0 + rr;
                unsigned lin = (unsigned)(h * HD + d) * NE + (unsigned)n;
                unsigned ne2 = lin / C_;
                unsigned cz  = lin - ne2 * C_;
                unsigned nf3 = ne2 * S_ + (unsigned)sP;
                AOb[(size_t)nf3 * C_ + cz] = v;
            }
        }
    }
}

// ---------------- K5: BN stats (deterministic, float4) ----------------
__global__ __launch_bounds__(256) void bn_stats()
{
    const int o = blockIdx.x;
    const int t = threadIdx.x;
    float s = 0.f, sq = 0.f;
#pragma unroll 4
    for (int k = 0; k < 32; k++) {
        int u = t + k * 256;
        int b = u >> 8, n4 = (u & 255) * 4;
        float4 v = *(const float4*)(g_P + ((size_t)b * C_ + o) * N_ + n4);
        s  += v.x + v.y + v.z + v.w;
        sq += v.x * v.x + v.y * v.y + v.z * v.z + v.w * v.w;
    }
    __shared__ float rs_[256], rq[256];
    rs_[t] = s; rq[t] = sq;
    __syncthreads();
    for (int st = 128; st > 0; st >>= 1) {
        if (t < st) { rs_[t] += rs_[t + st]; rq[t] += rq[t + st]; }
        __syncthreads();
    }
    if (t == 0) {
        float inv_n = 1.f / (float)(B_ * N_);
        float mu  = rs_[0] * inv_n;
        float var = rq[0] * inv_n - mu * mu;
        g_mean[o] = mu;
        g_rstd[o] = rsqrtf(var + EPS_);
    }
}

// ---------------- K6: residual + BN normalize (float4) ----------------
__global__ __launch_bounds__(256) void final_kernel(
    const float* __restrict__ x,
    const float* __restrict__ gamma,
    const float* __restrict__ beta,
    float* __restrict__ out)
{
    int idx = (blockIdx.x * 256 + threadIdx.x) * 4;
    int c = (idx / N_) % C_;
    float ga = gamma[c], be = beta[c], mu = g_mean[c], rs = g_rstd[c];
    float4 v = *(const float4*)(g_P + idx);
    float4 xv = *(const float4*)(x + idx);
    float4 r;
    r.x = xv.x + ga * (v.x - mu) * rs + be;
    r.y = xv.y + ga * (v.y - mu) * rs + be;
    r.z = xv.z + ga * (v.z - mu) * rs + be;
    r.w = xv.w + ga * (v.w - mu) * rs + be;
    *(float4*)(out + idx) = r;
}

// ---------------- launch ----------------
extern "C" void kernel_launch(void* const* d_in, const int* in_sizes, int n_in,
                              void* d_out, int out_size)
{
    const float* x     = (const float*)d_in[0];
    const float* Wq    = (const float*)d_in[1];
    const float* Wk    = (const float*)d_in[2];
    const float* Wv    = (const float*)d_in[3];
    const float* Wpe   = (const float*)d_in[4];
    const float* Wproj = (const float*)d_in[5];
    const float* gamma = (const float*)d_in[6];
    const float* beta  = (const float*)d_in[7];
    float* out = (float*)d_out;

    static bool attr_set = false;
    if (!attr_set) {
        cudaFuncSetAttribute(qkv_mma, cudaFuncAttributeMaxDynamicSharedMemorySize,
                             GS_FLOATS * (int)sizeof(float));
        cudaFuncSetAttribute(proj_mma, cudaFuncAttributeMaxDynamicSharedMemorySize,
                             PS_FLOATS * (int)sizeof(float));
        cudaFuncSetAttribute(attn_flash, cudaFuncAttributeMaxDynamicSharedMemorySize,
                             ATT_FLOATS * (int)sizeof(float));
        attr_set = true;
    }

    qkv_mma<<<dim3(N_ / 128, 9, B_), 256, GS_FLOATS * sizeof(float)>>>(Wq, Wk, Wv, x);

    dwconv_smem<<<B_ * C_, 256>>>(Wpe);

    attn_flash<<<dim3(4, NHEAD, 128), 256, ATT_FLOATS * sizeof(float)>>>();

    proj_mma<<<dim3(N_ / 128, C_ / 128, B_), 256, PS_FLOATS * sizeof(float)>>>(Wproj);

    bn_stats<<<C_, 256>>>();

    final_kernel<<<(B_ * C_ * N_) / 1024, 256>>>(x, gamma, beta, out);
}